// round 5
// baseline (speedup 1.0000x reference)
#include <cuda_runtime.h>
#include <cuda_bf16.h>
#include <math.h>

// Problem constants
#define BATCH   512
#define DIM     256
#define NTREES  512
#define DEPTH   6
#define UNITS   3
#define NLEAVES 64
#define NCOLS   (NTREES * DEPTH)   // 3072 sparsemax columns
#define MAXC    128                // max sparsemax support per column
#define CPB     16                 // sparsemax columns per prep block
#define NSMX    (NCOLS / CPB)      // 192 sparsemax blocks

// -------- device scratch (no dynamic allocation allowed) --------
__device__ float  g_xT[DIM * BATCH];      // transposed x: (DIM, BATCH)
__device__ int    g_nnz[NCOLS];           // support size per column
__device__ float2 g_sel[NCOLS * MAXC];    // interleaved (idx*BATCH as int bits, weight)

// ============================================================================
// Kernel A: blocks [0, 192): 8 warps/block, TWO sparsemax columns per warp
//   (interleaved shuffle chains double ILP on the serial reductions).
//   Michelot projection warm-started at tau0 = max(z) - 1 (valid since
//   tau* >= zmax - 1): support starts ~7 instead of 256 -> ~2-3 iterations.
// blocks [192, 320): 32x32 tiled transpose of x -> g_xT.
// ============================================================================
__global__ void __launch_bounds__(256)
prep_kernel(const float* __restrict__ x,
            const float* __restrict__ fsl)
{
    const int bid = blockIdx.x;
    const int tid = threadIdx.x;

    if (bid < NSMX) {
        __shared__ float s_z[DIM][CPB + 1];   // pad 17: conflict-free
        const int warp = tid >> 5;
        const int lane = tid & 31;
        const int col0 = bid * CPB;

        // coalesced staging: 16 consecutive cols x 4B = 64B packed sectors
        {
            const int c  = tid & 15;
            const int ib = tid >> 4;
            #pragma unroll
            for (int iter = 0; iter < 16; iter++) {
                const int i = iter * 16 + ib;
                s_z[i][c] = fsl[i * NCOLS + col0 + c];
            }
        }
        __syncthreads();

        const int colA = col0 + warp * 2;
        const int colB = colA + 1;

        float za[8], zb[8];
        #pragma unroll
        for (int j = 0; j < 8; j++) {
            za[j] = s_z[j * 32 + lane][warp * 2];
            zb[j] = s_z[j * 32 + lane][warp * 2 + 1];
        }

        // per-column max -> warm start
        float m0 = za[0], m1 = zb[0];
        #pragma unroll
        for (int j = 1; j < 8; j++) {
            m0 = fmaxf(m0, za[j]);
            m1 = fmaxf(m1, zb[j]);
        }
        #pragma unroll
        for (int o = 16; o > 0; o >>= 1) {
            m0 = fmaxf(m0, __shfl_xor_sync(0xffffffffu, m0, o));
            m1 = fmaxf(m1, __shfl_xor_sync(0xffffffffu, m1, o));
        }
        float tau0 = m0 - 1.0f;
        float tau1 = m1 - 1.0f;

        // Michelot: tau <- (sum_{z>tau} z - 1)/k until both supports stable
        int k0p = -1, k1p = -1;
        #pragma unroll 1
        for (int it = 0; it < 16; it++) {
            float s0 = 0.0f, s1 = 0.0f;
            int   k0 = 0,   k1 = 0;
            #pragma unroll
            for (int j = 0; j < 8; j++) {
                if (za[j] > tau0) { s0 += za[j]; k0++; }
                if (zb[j] > tau1) { s1 += zb[j]; k1++; }
            }
            #pragma unroll
            for (int o = 16; o > 0; o >>= 1) {
                s0 += __shfl_xor_sync(0xffffffffu, s0, o);
                s1 += __shfl_xor_sync(0xffffffffu, s1, o);
                k0 += __shfl_xor_sync(0xffffffffu, k0, o);
                k1 += __shfl_xor_sync(0xffffffffu, k1, o);
            }
            if (k0 == k0p && k1 == k1p) break;
            k0p = k0; k1p = k1;
            tau0 = (s0 - 1.0f) / (float)k0;
            tau1 = (s1 - 1.0f) / (float)k1;
        }

        // compact nonzero weights, interleaved (idx*BATCH, w)
        int base = 0;
        #pragma unroll
        for (int j = 0; j < 8; j++) {
            const bool nz = (za[j] > tau0);
            const unsigned m = __ballot_sync(0xffffffffu, nz);
            if (nz) {
                int pos = base + __popc(m & ((1u << lane) - 1u));
                g_sel[colA * MAXC + pos] =
                    make_float2(__int_as_float((j * 32 + lane) * BATCH), za[j] - tau0);
            }
            base += __popc(m);
        }
        if (lane == 0) g_nnz[colA] = base;

        base = 0;
        #pragma unroll
        for (int j = 0; j < 8; j++) {
            const bool nz = (zb[j] > tau1);
            const unsigned m = __ballot_sync(0xffffffffu, nz);
            if (nz) {
                int pos = base + __popc(m & ((1u << lane) - 1u));
                g_sel[colB * MAXC + pos] =
                    make_float2(__int_as_float((j * 32 + lane) * BATCH), zb[j] - tau1);
            }
            base += __popc(m);
        }
        if (lane == 0) g_nnz[colB] = base;
    } else {
        // transpose x (BATCH=512, DIM=256) -> g_xT (DIM, BATCH)
        __shared__ float tile[32][33];
        const int t  = bid - NSMX;
        const int bt = t & 15;
        const int it = t >> 4;
        const int tx = tid & 31;
        const int ty = tid >> 5;
        #pragma unroll
        for (int r = 0; r < 4; r++) {
            int row = ty + r * 8;
            tile[row][tx] = x[(bt * 32 + row) * DIM + it * 32 + tx];
        }
        __syncthreads();
        #pragma unroll
        for (int r = 0; r < 4; r++) {
            int row = ty + r * 8;
            g_xT[(it * 32 + row) * BATCH + bt * 32 + tx] = tile[tx][row];
        }
    }
}

// ============================================================================
// Kernel B: fused gather + forest. 2048 blocks x 128 threads;
// block = (tree n, quarter of batch). Gather fv inline (12 loads in flight),
// then gates -> factored leaf probs -> response dot.
// ============================================================================
__global__ void __launch_bounds__(128, 10)
forest_kernel(const float* __restrict__ th,    // (NTREES, DEPTH)
              const float* __restrict__ lt,    // (NTREES, DEPTH)
              const float* __restrict__ resp,  // (NTREES, UNITS, NLEAVES)
              float* __restrict__ out)         // (BATCH, NTREES, UNITS)
{
    const int n   = blockIdx.x >> 2;
    const int bq  = blockIdx.x & 3;
    const int tid = threadIdx.x;
    const int b   = bq * 128 + tid;

    __shared__ float4 s_resp4[UNITS * NLEAVES / 4];   // 48 x float4
    __shared__ float  s_th[DEPTH];
    __shared__ float  s_et[DEPTH];
    __shared__ int    s_cnt[8];
    __shared__ float2 s_list[DEPTH][MAXC];            // 6 KB

    if (tid < UNITS * NLEAVES / 4)
        s_resp4[tid] = ((const float4*)resp)[n * (UNITS * NLEAVES / 4) + tid];
    if (tid >= 64 && tid < 64 + DEPTH) {
        const int d = tid - 64;
        s_th[d]  = th[n * DEPTH + d];
        s_et[d]  = __expf(-lt[n * DEPTH + d]);
        s_cnt[d] = g_nnz[n * DEPTH + d];
    }
    __syncthreads();

    // common padded length (even)
    int cm = 0;
    #pragma unroll
    for (int d = 0; d < DEPTH; d++) cm = max(cm, s_cnt[d]);
    cm = (cm + 1) & ~1;

    #pragma unroll
    for (int d = 0; d < DEPTH; d++) {
        const int cnt = s_cnt[d];
        const int col = n * DEPTH + d;
        for (int j = tid; j < cm; j += 128) {
            float2 e = make_float2(__int_as_float(0), 0.0f);
            if (j < cnt) e = g_sel[col * MAXC + j];
            s_list[d][j] = e;
        }
    }
    __syncthreads();

    // inline gather: fv[d] = sum_j w * xT[idx][b]; 12 independent loads/iter
    const float* xb = g_xT + b;
    float fv[DEPTH];
    #pragma unroll
    for (int d = 0; d < DEPTH; d++) fv[d] = 0.0f;

    #pragma unroll 1
    for (int j = 0; j < cm; j += 2) {
        #pragma unroll
        for (int jj = 0; jj < 2; jj++) {
            #pragma unroll
            for (int d = 0; d < DEPTH; d++) {
                float2 e = s_list[d][j + jj];
                fv[d] += e.y * xb[__float_as_int(e.x)];
            }
        }
    }

    // gates
    float g[DEPTH];
    #pragma unroll
    for (int d = 0; d < DEPTH; d++)
        g[d] = __saturatef(0.5f * ((fv[d] - s_th[d]) * s_et[d]) + 0.5f);

    // leaf prob factorization: p_c = qlo[c&7] * qhi[c>>3]
    float qlo[8], qhi[8];
    #pragma unroll
    for (int c = 0; c < 8; c++) {
        float p0 = (c & 1) ? (1.0f - g[0]) : g[0];
        float p1 = (c & 2) ? (1.0f - g[1]) : g[1];
        float p2 = (c & 4) ? (1.0f - g[2]) : g[2];
        qlo[c] = p0 * p1 * p2;
        float p3 = (c & 1) ? (1.0f - g[3]) : g[3];
        float p4 = (c & 2) ? (1.0f - g[4]) : g[4];
        float p5 = (c & 4) ? (1.0f - g[5]) : g[5];
        qhi[c] = p3 * p4 * p5;
    }

    // response contraction
    float acc0 = 0.0f, acc1 = 0.0f, acc2 = 0.0f;
    #pragma unroll
    for (int hi = 0; hi < 8; hi++) {
        const float qh = qhi[hi];
        #pragma unroll
        for (int u = 0; u < UNITS; u++) {
            float4 a = s_resp4[(u * NLEAVES + hi * 8) / 4];
            float4 c = s_resp4[(u * NLEAVES + hi * 8) / 4 + 1];
            float t = a.x * qlo[0] + a.y * qlo[1] + a.z * qlo[2] + a.w * qlo[3]
                    + c.x * qlo[4] + c.y * qlo[5] + c.z * qlo[6] + c.w * qlo[7];
            if (u == 0) acc0 += qh * t;
            else if (u == 1) acc1 += qh * t;
            else acc2 += qh * t;
        }
    }

    float* o = out + ((size_t)b * NTREES + n) * UNITS;
    o[0] = acc0;
    o[1] = acc1;
    o[2] = acc2;
}

// ============================================================================
extern "C" void kernel_launch(void* const* d_in, const int* in_sizes, int n_in,
                              void* d_out, int out_size)
{
    const float* x    = (const float*)d_in[0];  // (512, 256)
    const float* fsl  = (const float*)d_in[1];  // (256, 512, 6)
    const float* th   = (const float*)d_in[2];  // (512, 6)
    const float* lt   = (const float*)d_in[3];  // (512, 6)
    const float* resp = (const float*)d_in[4];  // (512, 3, 64)
    float* out = (float*)d_out;                 // (512, 512, 3)

    prep_kernel<<<NSMX + 128, 256>>>(x, fsl);
    forest_kernel<<<NTREES * 4, 128>>>(th, lt, resp, out);
}